// round 15
// baseline (speedup 1.0000x reference)
#include <cuda_runtime.h>
#include <cuda_bf16.h>
#include <math.h>
#include <stdint.h>

#define L 256
#define D 1024
#define H 16
#define DH 64
#define LD (L*D)

// ---------------- device scratch (no allocations allowed) ----------------
__device__ __align__(16) __nv_bfloat16 g_act_hi[2*LD];   // mu, var  [m][k]
__device__ __align__(16) __nv_bfloat16 g_act_lo[2*LD];
__device__ __align__(16) __nv_bfloat16 g_O_hi[2*LD];     // Om, Ov bf16 splits
__device__ __align__(16) __nv_bfloat16 g_O_lo[2*LD];
__device__ float g_qkv_part[2*6*LD];   // [ksplit][gemm][L*D]
__device__ float g_out_part[4*2*LD];   // [ksplit][gemm][L*D]
// attention feature arrays (bf16 splits), layout [l][h][128]
__device__ __align__(16) __nv_bfloat16 g_Xq_hi[L*2048], g_Xq_lo[L*2048];
__device__ __align__(16) __nv_bfloat16 g_Xk_hi[L*2048], g_Xk_lo[L*2048];
// transposed V: [g(m/v)][h*64+d][l]
__device__ __align__(16) __nv_bfloat16 g_VT_hi[2*1024*L], g_VT_lo[2*1024*L];
__device__ float g_Ck[H*L];

// ---------------- helpers ----------------
__device__ __forceinline__ uint32_t smem_u32(const void* p) {
    uint32_t a;
    asm("{ .reg .u64 t; cvta.to.shared.u64 t, %1; cvt.u32.u64 %0, t; }" : "=r"(a) : "l"(p));
    return a;
}
__device__ __forceinline__ void ldsm_x4(uint32_t (&r)[4], uint32_t addr) {
    asm volatile("ldmatrix.sync.aligned.m8n8.x4.shared.b16 {%0,%1,%2,%3}, [%4];"
                 : "=r"(r[0]), "=r"(r[1]), "=r"(r[2]), "=r"(r[3]) : "r"(addr));
}
__device__ __forceinline__ void mma_bf16(float (&d)[4], const uint32_t (&a)[4],
                                         uint32_t b0, uint32_t b1) {
    asm volatile(
        "mma.sync.aligned.m16n8k16.row.col.f32.bf16.bf16.f32 "
        "{%0,%1,%2,%3}, {%4,%5,%6,%7}, {%8,%9}, {%0,%1,%2,%3};"
        : "+f"(d[0]), "+f"(d[1]), "+f"(d[2]), "+f"(d[3])
        : "r"(a[0]), "r"(a[1]), "r"(a[2]), "r"(a[3]), "r"(b0), "r"(b1));
}
__device__ __forceinline__ float softplusf(float x) {
    return fmaxf(x, 0.0f) + log1pf(expf(-fabsf(x)));
}
__device__ __forceinline__ void split_bf16(float f, __nv_bfloat16& hi, __nv_bfloat16& lo) {
    hi = __float2bfloat16(f);
    lo = __float2bfloat16(f - __bfloat162float(hi));
}
__device__ __forceinline__ void pack_pair(float a0, float a1, uint32_t& uhi, uint32_t& ulo) {
    union { __nv_bfloat16 b[2]; uint32_t u; } Hi, Lo;
    split_bf16(a0, Hi.b[0], Lo.b[0]);
    split_bf16(a1, Hi.b[1], Lo.b[1]);
    uhi = Hi.u; ulo = Lo.u;
}
__device__ __forceinline__ void cp16(uint32_t smem_dst, const void* gsrc) {
    asm volatile("cp.async.cg.shared.global [%0], [%1], 16;"
                 :: "r"(smem_dst), "l"(gsrc) : "memory");
}
#define CP_COMMIT() asm volatile("cp.async.commit_group;" ::: "memory")
#define CP_WAIT(n)  asm volatile("cp.async.wait_group %0;" :: "n"(n) : "memory")

// ---------------- HMMA bf16x3 GEMM: cp.async A, fused fp32->bf16 W split ----
#define BK 32
#define PITCH 40
#define S_AHI 0
#define S_ALO (128*PITCH)
#define S_BHI (2*128*PITCH)
#define S_BLO (2*128*PITCH + 64*PITCH)
#define STAGE_H (2*128*PITCH + 2*64*PITCH)
#define GEMM_SMEM_B (2*STAGE_H*2)

__device__ void gemm_mma(const float* __restrict__ W,
                         const __nv_bfloat16* __restrict__ a_hi,
                         const __nv_bfloat16* __restrict__ a_lo,
                         float* __restrict__ Cpart,
                         int m0, int n0, int k0, int nchunks)
{
    extern __shared__ __nv_bfloat16 sh[];
    const uint32_t sbase = smem_u32(sh);
    const int tid = threadIdx.x;
    const int lane = tid & 31;
    const int wid  = tid >> 5;
    const int wm   = wid & 3;
    const int wn   = wid >> 2;

    float acc[2][4][4];
    #pragma unroll
    for (int mt = 0; mt < 2; mt++)
        #pragma unroll
        for (int nt = 0; nt < 4; nt++)
            #pragma unroll
            for (int r = 0; r < 4; r++) acc[mt][nt][r] = 0.0f;

    const int arow = tid >> 2;
    const int ac8  = (tid & 3) << 3;
    const int bn   = tid & 63;
    const int bkb  = (tid >> 6) << 3;

    float bw[8];

    // A-operand: direct cp.async global->shared (no conversion needed)
    auto CPA = [&](int c, int buf) {
        const int kg = k0 + c * BK;
        const uint32_t dbase = sbase + (uint32_t)buf * (STAGE_H * 2);
        #pragma unroll
        for (int u = 0; u < 2; u++) {
            const size_t off = (size_t)(m0 + arow + u * 64) * D + kg + ac8;
            const uint32_t d = dbase + (uint32_t)((arow + u * 64) * PITCH + ac8) * 2;
            cp16(d,                 a_hi + off);
            cp16(d + S_ALO * 2,     a_lo + off);
        }
        CP_COMMIT();
    };
    // W: LDG fp32, split in registers
    auto LDGW = [&](int c) {
        const int kg = k0 + c * BK;
        const float* wp = W + (size_t)(kg + bkb) * D + n0 + bn;
        #pragma unroll
        for (int i = 0; i < 8; i++) bw[i] = wp[(size_t)i * D];
    };
    auto STSW = [&](int buf) {
        __nv_bfloat16* s = sh + buf * STAGE_H;
        union { __nv_bfloat16 h[8]; uint4 u; } Hi, Lo;
        #pragma unroll
        for (int i = 0; i < 8; i++) split_bf16(bw[i], Hi.h[i], Lo.h[i]);
        const int boff = bn * PITCH + bkb;
        *(uint4*)(s + S_BHI + boff) = Hi.u;
        *(uint4*)(s + S_BLO + boff) = Lo.u;
    };

    const uint32_t a_lrow = (uint32_t)(wm * 32 + (lane & 15)) * PITCH;
    const uint32_t a_koff = (uint32_t)((lane >> 4) << 3);
    const uint32_t b_lrow = (uint32_t)(wn * 32 + ((lane >> 4) << 3) + (lane & 7)) * PITCH;
    const uint32_t b_koff = (uint32_t)(((lane >> 3) & 1) << 3);

    CPA(0, 0); LDGW(0); STSW(0);
    CP_WAIT(0); __syncthreads();
    for (int c = 0; c < nchunks; c++) {
        const int cur = c & 1;
        if (c + 1 < nchunks) { CPA(c + 1, cur ^ 1); LDGW(c + 1); }
        const uint32_t sb = sbase + (uint32_t)cur * (STAGE_H * 2);
        #pragma unroll
        for (int ks = 0; ks < 2; ks++) {
            uint32_t ahi[2][4], alo[2][4], bhi[2][4], blo[2][4];
            #pragma unroll
            for (int mt = 0; mt < 2; mt++) {
                uint32_t ad = sb + (S_AHI + a_lrow + mt * 16 * PITCH + ks * 16 + a_koff) * 2;
                ldsm_x4(ahi[mt], ad);
                ldsm_x4(alo[mt], ad + (S_ALO - S_AHI) * 2);
            }
            #pragma unroll
            for (int p = 0; p < 2; p++) {
                uint32_t bd = sb + (S_BHI + b_lrow + p * 16 * PITCH + ks * 16 + b_koff) * 2;
                ldsm_x4(bhi[p], bd);
                ldsm_x4(blo[p], bd + (S_BLO - S_BHI) * 2);
            }
            #pragma unroll
            for (int mt = 0; mt < 2; mt++)
                #pragma unroll
                for (int nt = 0; nt < 4; nt++) {
                    const int p = nt >> 1, q = (nt & 1) * 2;
                    mma_bf16(acc[mt][nt], ahi[mt], bhi[p][q], bhi[p][q + 1]);
                    mma_bf16(acc[mt][nt], ahi[mt], blo[p][q], blo[p][q + 1]);
                    mma_bf16(acc[mt][nt], alo[mt], bhi[p][q], bhi[p][q + 1]);
                }
        }
        if (c + 1 < nchunks) { STSW(cur ^ 1); CP_WAIT(0); }
        __syncthreads();
    }

    #pragma unroll
    for (int mt = 0; mt < 2; mt++)
        #pragma unroll
        for (int nt = 0; nt < 4; nt++) {
            const int r = m0 + wm * 32 + mt * 16 + (lane >> 2);
            const int cL = n0 + wn * 32 + nt * 8 + (lane & 3) * 2;
            *(float2*)(Cpart + (size_t)r * D + cL) =
                make_float2(acc[mt][nt][0], acc[mt][nt][1]);
            *(float2*)(Cpart + (size_t)(r + 8) * D + cL) =
                make_float2(acc[mt][nt][2], acc[mt][nt][3]);
        }
}

// QKV: 6 GEMMs, split-K 2 -> grid(16, 4, 6) = 384 CTAs
__global__ __launch_bounds__(256, 2) void qkv_gemm_mma(
    const float* wqm, const float* wqv, const float* wkm,
    const float* wkv, const float* wvm, const float* wvv)
{
    const int g = blockIdx.z;
    const int mt = blockIdx.y & 1, s = blockIdx.y >> 1;
    const float* W;
    switch (g) {
        case 0: W = wqm; break; case 1: W = wqv; break;
        case 2: W = wkm; break; case 3: W = wkv; break;
        case 4: W = wvm; break; default: W = wvv; break;
    }
    gemm_mma(W, g_act_hi + (size_t)(g & 1) * LD, g_act_lo + (size_t)(g & 1) * LD,
             g_qkv_part + (size_t)(s * 6 + g) * LD,
             mt * 128, blockIdx.x * 64, s * 512, 16);
}

// out: 2 GEMMs, split-K 4 -> grid(16, 8, 2) = 256 CTAs
__global__ __launch_bounds__(256, 2) void out_gemm_mma(const float* wom, const float* wov)
{
    const int g = blockIdx.z;
    const int mt = blockIdx.y & 1, s = blockIdx.y >> 1;   // s in 0..3
    gemm_mma(g ? wov : wom,
             g_O_hi + (size_t)g * LD, g_O_lo + (size_t)g * LD,
             g_out_part + (size_t)(s * 2 + g) * LD,
             mt * 128, blockIdx.x * 64, s * 256, 8);
}

// ---------------- activation convert ----------------
__global__ __launch_bounds__(256) void convert_act_kernel(const float* mu, const float* var)
{
    int t = blockIdx.x * 256 + threadIdx.x;
    int e = t * 4;
    const float* src = (e < LD) ? mu : var;
    float4 v = *(const float4*)(src + (e & (LD - 1)));
    float vv[4] = { v.x, v.y, v.z, v.w };
    union { __nv_bfloat16 h[4]; uint2 u; } Hi, Lo;
    #pragma unroll
    for (int i = 0; i < 4; i++) split_bf16(vv[i], Hi.h[i], Lo.h[i]);
    *(uint2*)(g_act_hi + e) = Hi.u;
    *(uint2*)(g_act_lo + e) = Lo.u;
}

// ---------------- prep: sum 2 splits + bias + act + attn features ----------
__global__ __launch_bounds__(256) void prep_kernel(
    const float* bqm, const float* bqv, const float* bkm, const float* bkv,
    const float* bvm, const float* bvv)
{
    int tid = blockIdx.x * 256 + threadIdx.x;
    int e0  = tid * 2;
    int l = e0 >> 10, col = e0 & (D - 1);
    int h = col >> 6, dd = col & 63;

    float2 v[6];
    #pragma unroll
    for (int g = 0; g < 6; g++) {
        float2 p0 = *(const float2*)(g_qkv_part + (size_t)(0 * 6 + g) * LD + e0);
        float2 p1 = *(const float2*)(g_qkv_part + (size_t)(1 * 6 + g) * LD + e0);
        v[g] = make_float2(p0.x + p1.x, p0.y + p1.y);
    }
    float vals[6][2] = {
        { v[0].x + bqm[col], v[0].y + bqm[col + 1] },
        { v[1].x + bqv[col], v[1].y + bqv[col + 1] },
        { v[2].x + bkm[col], v[2].y + bkm[col + 1] },
        { v[3].x + bkv[col], v[3].y + bkv[col + 1] },
        { v[4].x + bvm[col], v[4].y + bvm[col + 1] },
        { v[5].x + bvv[col], v[5].y + bvv[col + 1] },
    };
    float Aq[2], nqm[2], f1[2], f2[2], vm[2], vvv[2];
    float c = 0.0f;
    #pragma unroll
    for (int u = 0; u < 2; u++) {
        float qm = vals[0][u];
        float qv = softplusf(vals[1][u]);
        float km = vals[2][u];
        float kv = softplusf(vals[3][u]);
        float inv = 1.0f / kv;
        Aq[u]  = 0.5f * (qm * qm + qv);
        nqm[u] = -qm;
        f1[u]  = inv;
        f2[u]  = km * inv;
        vm[u]  = vals[4][u];
        vvv[u] = softplusf(vals[5][u]);
        c += 0.5f * (km * km * inv + logf(kv));
    }

    size_t xq = (size_t)l * 2048 + h * 128 + dd;
    uint32_t uh, ul;
    pack_pair(Aq[0],  Aq[1],  uh, ul);
    *(uint32_t*)(g_Xq_hi + xq) = uh;  *(uint32_t*)(g_Xq_lo + xq) = ul;
    pack_pair(nqm[0], nqm[1], uh, ul);
    *(uint32_t*)(g_Xq_hi + xq + 64) = uh;  *(uint32_t*)(g_Xq_lo + xq + 64) = ul;
    pack_pair(f1[0],  f1[1],  uh, ul);
    *(uint32_t*)(g_Xk_hi + xq) = uh;  *(uint32_t*)(g_Xk_lo + xq) = ul;
    pack_pair(f2[0],  f2[1],  uh, ul);
    *(uint32_t*)(g_Xk_hi + xq + 64) = uh;  *(uint32_t*)(g_Xk_lo + xq + 64) = ul;

    size_t vr = (size_t)(h * 64 + dd) * L + l;
    __nv_bfloat16 bh, bl;
    split_bf16(vm[0],  bh, bl); g_VT_hi[vr]              = bh; g_VT_lo[vr]              = bl;
    split_bf16(vm[1],  bh, bl); g_VT_hi[vr + L]          = bh; g_VT_lo[vr + L]          = bl;
    split_bf16(vvv[0], bh, bl); g_VT_hi[262144 + vr]     = bh; g_VT_lo[262144 + vr]     = bl;
    split_bf16(vvv[1], bh, bl); g_VT_hi[262144 + vr + L] = bh; g_VT_lo[262144 + vr + L] = bl;

    #pragma unroll
    for (int off = 16; off; off >>= 1) c += __shfl_xor_sync(0xffffffffu, c, off);
    if ((threadIdx.x & 31) == 0) {
        int w = tid >> 5;
        int row = w >> 4, hh = w & 15;
        g_Ck[hh * L + row] = c;
    }
}

// ---------------- HMMA attention: per (q-tile-32, head) [R13 version] ------
// all offsets in halves unless noted
#define AP 40
#define CH_Q 1296     // 32*40+16
#define CH_K 10256    // 256*40+16
#define CH_V 2576     // 64*40+16
#define XQ_HI 0
#define XQ_LO 5184
#define XK_HI 10368
#define XK_LO 51392
#define P_HI  0
#define P_LO  10368
#define P2_HI 20736
#define P2_LO 31104
#define VM_HI 41472
#define VM_LO 51776
#define VV_HI 62080
#define VV_LO 72384
#define PVREDF 41344   // float index: [2][32][68]
#define REDF   46208   // float index: [32][9]
#define CKF    46496   // float index: [256]
#define ATTN_SMEM_BYTES 187008

__global__ __launch_bounds__(256) void attn_kernel()
{
    extern __shared__ __nv_bfloat16 sh[];
    float* shf = (float*)sh;
    const uint32_t sbase = smem_u32(sh);
    const int h = blockIdx.y, q0 = blockIdx.x * 32;
    const int tid = threadIdx.x, lane = tid & 31, wid = tid >> 5;
    const int r4 = lane >> 2;

    if (tid < 256) shf[CKF + tid] = g_Ck[h * L + tid];

    // ---- load Xq (32 rows) and Xk (256 rows), hi/lo, chunked k ----
    #pragma unroll
    for (int u = 0; u < 2; u++) {
        int idx = tid + u * 256;
        int row = idx >> 4, k = (idx & 15) * 8;
        int ch = k >> 5, wi = k & 31;
        size_t src = (size_t)(q0 + row) * 2048 + h * 128 + k;
        int dst = ch * CH_Q + row * AP + wi;
        *(uint4*)(sh + XQ_HI + dst) = *(const uint4*)(g_Xq_hi + src);
        *(uint4*)(sh + XQ_LO + dst) = *(const uint4*)(g_Xq_lo + src);
    }
    #pragma unroll
    for (int u = 0; u < 16; u++) {
        int idx = tid + u * 256;
        int row = idx >> 4, k = (idx & 15) * 8;
        int ch = k >> 5, wi = k & 31;
        size_t src = (size_t)row * 2048 + h * 128 + k;
        int dst = ch * CH_K + row * AP + wi;
        *(uint4*)(sh + XK_HI + dst) = *(const uint4*)(g_Xk_hi + src);
        *(uint4*)(sh + XK_LO + dst) = *(const uint4*)(g_Xk_lo + src);
    }
    __syncthreads();

    const uint32_t a_row = (uint32_t)(lane & 15) * AP;
    const uint32_t a_k   = (uint32_t)(lane >> 4) * 8;
    const uint32_t b_pat = (uint32_t)(((lane >> 4) << 3) + (lane & 7));
    const uint32_t b_k   = (uint32_t)((lane >> 3) & 1) * 8;
    const uint32_t b_row = (uint32_t)(wid * 32 + b_pat) * AP;

    // ---- scores S = Xq . Xk^T ----
    float acc[2][4][4];
    #pragma unroll
    for (int mt = 0; mt < 2; mt++)
        #pragma unroll
        for (int nt = 0; nt < 4; nt++)
            #pragma unroll
            for (int r = 0; r < 4; r++) acc[mt][nt][r] = 0.0f;

    #pragma unroll
    for (int c = 0; c < 4; c++)
        #pragma unroll
        for (int ks = 0; ks < 2; ks++) {
            uint32_t ahi[2][4], alo[2][4], bhi[2][4], blo[2][4];
            #pragma unroll
            for (int mt = 0; mt < 2; mt++) {
                uint32_t ad = sbase + (uint32_t)(XQ_HI + c * CH_Q + a_row + mt * 16 * AP + ks * 16 + a_k) * 2;
                ldsm_x4(ahi[mt], ad);
                ldsm_x4(alo[mt], ad + (XQ_LO - XQ_HI) * 2);
            }
            #pragma unroll
            for (int p = 0; p < 2; p++) {
                uint32_t bd = sbase + (uint32_t)(XK_HI + c * CH_K + b_row + p * 16 * AP + ks * 16 + b_k) * 2;
                ldsm_x4(bhi[p], bd);
                ldsm_x4(blo[p], bd + (XK_LO - XK_HI) * 2);
            }
            #pragma unroll
            for (int mt = 0; mt < 2; mt++)
                #pragma unroll
                for (int nt = 0; nt < 4; nt++) {
                    const int p = nt >> 1, q = (nt & 1) * 2;
                    mma_bf16(acc[mt][nt], ahi[mt], bhi[p][q], bhi[p][q + 1]);
                    mma_bf16(acc[mt][nt], ahi[mt], blo[p][q], blo[p][q + 1]);
                    mma_bf16(acc[mt][nt], alo[mt], bhi[p][q], bhi[p][q + 1]);
                }
        }

    // ---- s = -0.125*(acc + Ck[col]) ----
    #pragma unroll
    for (int nt = 0; nt < 4; nt++) {
        int c0 = wid * 32 + nt * 8 + (lane & 3) * 2;
        float ck0 = shf[CKF + c0], ck1 = shf[CKF + c0 + 1];
        #pragma unroll
        for (int mt = 0; mt < 2; mt++) {
            acc[mt][nt][0] = -0.125f * (acc[mt][nt][0] + ck0);
            acc[mt][nt][1] = -0.125f * (acc[mt][nt][1] + ck1);
            acc[mt][nt][2] = -0.125f * (acc[mt][nt][2] + ck0);
            acc[mt][nt][3] = -0.125f * (acc[mt][nt][3] + ck1);
        }
    }

    // ---- softmax over 256 cols (8 warps) ----
    float rmax[2][2], rinv[2][2];
    #pragma unroll
    for (int mt = 0; mt < 2; mt++)
        #pragma unroll
        for (int rh = 0; rh < 2; rh++) {
            float m = -1e30f;
            #pragma unroll
            for (int nt = 0; nt < 4; nt++)
                m = fmaxf(m, fmaxf(acc[mt][nt][rh * 2], acc[mt][nt][rh * 2 + 1]));
            m = fmaxf(m, __shfl_xor_sync(0xffffffffu, m, 1));
            m = fmaxf(m, __shfl_xor_sync(0xffffffffu, m, 2));
            if ((lane & 3) == 0)
                shf[REDF + (mt * 16 + rh * 8 + r4) * 9 + wid] = m;
        }
    __syncthreads();
    #pragma unroll
    for (int mt = 0; mt < 2; mt++)
        #pragma unroll
        for (int rh = 0; rh < 2; rh++) {
            int row = mt * 16 + rh * 8 + r4;
            float m = -1e30f;
            #pragma unroll
            for (int w = 0; w < 8; w++) m = fmaxf(m, shf[REDF + row * 9 + w]);
            rmax[mt][rh] = m;
        }
    __syncthreads();
    #pragma unroll
    for (int mt = 0; mt < 2; mt++)
        #pragma unroll
        for (int rh = 0; rh < 2; rh++) {
            float s = 0.0f;
            #pragma unroll
            for (int nt = 0; nt < 4; nt++) {
                float e0 = __expf(acc[mt][nt][rh * 2]     - rmax[mt][rh]);
                float e1 = __expf(acc[mt][nt][rh * 2 + 1] - rmax[mt][rh]);
                acc[mt][nt][rh * 2] = e0; acc[mt][nt][rh * 2 + 1] = e1;
                s += e0 + e1;
            }
            s += __shfl_xor_sync(0xffffffffu, s, 1);
            s += __shfl_xor_sync(0xffffffffu, s, 2);
            if ((lane & 3) == 0)
                shf[REDF + (mt * 16 + rh * 8 + r4) * 9 + wid] = s;
        }
    __syncthreads();
    #pragma unroll
    for (int mt = 0; mt < 2; mt++)
        #pragma unroll
        for (int rh = 0; rh < 2; rh++) {
            int row = mt * 16 + rh * 8 + r4;
            float s = 0.0f;
            #pragma unroll
            for (int w = 0; w < 8; w++) s += shf[REDF + row * 9 + w];
            rinv[mt][rh] = 1.0f / s;
        }

    // ---- write P, P^2 (hi/lo bf16) as A-operand chunks ----
    #pragma unroll
    for (int mt = 0; mt < 2; mt++)
        #pragma unroll
        for (int nt = 0; nt < 4; nt++) {
            int c0 = wid * 32 + nt * 8 + (lane & 3) * 2;
            int chp = c0 >> 5, wip = c0 & 31;
            #pragma unroll
            for (int rh = 0; rh < 2; rh++) {
                int row = mt * 16 + rh * 8 + r4;
                float pn0 = acc[mt][nt][rh * 2]     * rinv[mt][rh];
                float pn1 = acc[mt][nt][rh * 2 + 1] * rinv[mt][rh];
                uint32_t uh, ul;
                int ad = chp * CH_Q + row * AP + wip;
                pack_pair(pn0, pn1, uh, ul);
                *(uint32_t*)(sh + P_HI + ad) = uh;
                *(uint32_t*)(sh + P_LO + ad) = ul;
                pack_pair(pn0 * pn0, pn1 * pn1, uh, ul);
                *(uint32_t*)(sh + P2_HI + ad) = uh;
                *(uint32_t*)(sh + P2_LO + ad) = ul;
            }
        }
    __syncthreads();

    // ---- PV: out = P@Vm^T, P^2@Vv^T ----
    const int osel = wid >> 2, wkk = (wid >> 1) & 1, wn = wid & 1;
    const uint32_t PB_HI = osel ? P2_HI : P_HI;
    const uint32_t VB_HI = osel ? VV_HI : VM_HI;
    const uint32_t pv_brow = (uint32_t)(wn * 32 + b_pat) * AP;

    float acc2[2][4][4];
    #pragma unroll
    for (int mt = 0; mt < 2; mt++)
        #pragma unroll
        for (int nt = 0; nt < 4; nt++)
            #pragma unroll
            for (int r = 0; r < 4; r++) acc2[mt][nt][r] = 0.0f;

    for (int kp = 0; kp < 2; kp++) {
        if (kp) __syncthreads();
        #pragma unroll
        for (int u = 0; u < 4; u++) {
            int idx = tid + u * 256;
            int row = idx >> 4, k = (idx & 15) * 8;
            int ch = k >> 5, wi = k & 31;
            size_t src = (size_t)(h * 64 + row) * L + kp * 128 + k;
            int dst = ch * CH_V + row * AP + wi;
            *(uint4*)(sh + VM_HI + dst) = *(const uint4*)(g_VT_hi + src);
            *(uint4*)(sh + VM_LO + dst) = *(const uint4*)(g_VT_lo + src);
            *(uint4*)(sh + VV_HI + dst) = *(const uint4*)(g_VT_hi + 262144 + src);
            *(uint4*)(sh + VV_LO + dst) = *(const uint4*)(g_VT_lo + 262144 + src);
        }
        __syncthreads();
        #pragma unroll
        for (int c2 = 0; c2 < 2; c2++) {
            int gch = kp * 4 + wkk * 2 + c2;
            int lch = wkk * 2 + c2;
            #pragma unroll
            for (int ks = 0; ks < 2; ks++) {
                uint32_t phi[2][4], plo[2][4], vhi[2][4], vlo[2][4];
                #pragma unroll
                for (int mt = 0; mt < 2; mt++) {
                    uint32_t ad = sbase + (uint32_t)(PB_HI + gch * CH_Q + a_row + mt * 16 * AP + ks * 16 + a_k) * 2;
                    ldsm_x4(phi[mt], ad);
                    ldsm_x4(plo[mt], ad + (P_LO - P_HI) * 2);
                }
                #pragma unroll
                for (int p = 0; p < 2; p++) {
                    uint32_t bd = sbase + (uint32_t)(VB_HI + lch * CH_V + pv_brow + p * 16 * AP + ks * 16 + b_k) * 2;
                    ldsm_x4(vhi[p], bd);
                    ldsm_x4(vlo[p], bd + (VM_LO - VM_HI) * 2);
                }
                #pragma unroll
                for (int mt = 0; mt < 2; mt++)
                    #pragma unroll
                    for (int nt = 0; nt < 4; nt++) {
                        const int p = nt >> 1, q = (nt & 1) * 2;
                        mma_bf16(acc2[mt][nt], phi[mt], vhi[p][q], vhi[p][q + 1]);
                        mma_bf16(acc2[mt][nt], phi[mt], vlo[p][q], vlo[p][q + 1]);
                        mma_bf16(acc2[mt][nt], plo[mt], vhi[p][q], vhi[p][q + 1]);
                    }
            }
        }
    }
    __syncthreads();

    // ---- cross-warp k reduce + output ----
    if (wkk == 1) {
        #pragma unroll
        for (int mt = 0; mt < 2; mt++)
            #pragma unroll
            for (int nt = 0; nt < 4; nt++) {
                int row = mt * 16 + r4;
                int c0 = wn * 32 + nt * 8 + (lane & 3) * 2;
                int o = (osel * 32 + row) * 68 + c0;
                *(float2*)&shf[PVREDF + o] = make_float2(acc2[mt][nt][0], acc2[mt][nt][1]);
                *(float2*)&shf[PVREDF + o + 8 * 68] = make_float2(acc2[mt][nt][2], acc2[mt][nt][3]);
            }
    }
    __syncthreads();
    if (wkk == 0) {
        #pragma unroll
        for (int mt = 0; mt < 2; mt++)
            #pragma unroll
            for (int nt = 0; nt < 4; nt++) {
                int c0 = wn * 32 + nt * 8 + (lane & 3) * 2;
                #pragma unroll
                for (int rh = 0; rh < 2; rh++) {
                    int row = mt * 16 + rh * 8 + r4;
                    int o = (osel * 32 + row) * 68 + c0;
                    float v0 = acc2[mt][nt][rh * 2]     + shf[PVREDF + o];
                    float v1 = acc2[mt][nt][rh * 2 + 1] + shf[PVREDF + o + 1];
                    uint32_t uh, ul;
                    pack_pair(v0, v1, uh, ul);
                    size_t go = (size_t)osel * LD + (size_t)(q0 + row) * D + h * 64 + c0;
                    *(uint32_t*)(g_O_hi + go) = uh;
                    *(uint32_t*)(g_O_lo + go) = ul;
                }
            }
    }
}

// ---------------- output epilogue: sum 4 splits + bias + softplus ----------
__global__ __launch_bounds__(256) void out_epilogue_kernel(
    const float* bom, const float* bov, float* out)
{
    int g = blockIdx.y;
    int e = (blockIdx.x * 256 + threadIdx.x) * 4;
    float4 acc = make_float4(0.f, 0.f, 0.f, 0.f);
    #pragma unroll
    for (int s = 0; s < 4; s++) {
        float4 p = *(const float4*)(g_out_part + (size_t)(s * 2 + g) * LD + e);
        acc.x += p.x; acc.y += p.y; acc.z += p.z; acc.w += p.w;
    }
    int col = e & (D - 1);
    const float* b = g ? bov : bom;
    acc.x += b[col]; acc.y += b[col + 1]; acc.z += b[col + 2]; acc.w += b[col + 3];
    if (g) {
        acc.x = softplusf(acc.x); acc.y = softplusf(acc.y);
        acc.z = softplusf(acc.z); acc.w = softplusf(acc.w);
    }
    *(float4*)(out + (size_t)g * LD + e) = acc;
}

// ---------------- launch ----------------
extern "C" void kernel_launch(void* const* d_in, const int* in_sizes, int n_in,
                              void* d_out, int out_size)
{
    const float* mu  = (const float*)d_in[0];
    const float* var = (const float*)d_in[1];
    const float* wqm = (const float*)d_in[2],  * bqm = (const float*)d_in[3];
    const float* wqv = (const float*)d_in[4],  * bqv = (const float*)d_in[5];
    const float* wkm = (const float*)d_in[6],  * bkm = (const float*)d_in[7];
    const float* wkv = (const float*)d_in[8],  * bkv = (const float*)d_in[9];
    const float* wvm = (const float*)d_in[10], * bvm = (const float*)d_in[11];
    const float* wvv = (const float*)d_in[12], * bvv = (const float*)d_in[13];
    const float* wom = (const float*)d_in[14], * bom = (const float*)d_in[15];
    const float* wov = (const float*)d_in[16], * bov = (const float*)d_in[17];
    float* out = (float*)d_out;

    cudaFuncSetAttribute(qkv_gemm_mma, cudaFuncAttributeMaxDynamicSharedMemorySize, GEMM_SMEM_B);
    cudaFuncSetAttribute(out_gemm_mma, cudaFuncAttributeMaxDynamicSharedMemorySize, GEMM_SMEM_B);
    cudaFuncSetAttribute(attn_kernel, cudaFuncAttributeMaxDynamicSharedMemorySize, ATTN_SMEM_BYTES);

    convert_act_kernel<<<512, 256>>>(mu, var);
    qkv_gemm_mma<<<dim3(16, 4, 6), 256, GEMM_SMEM_B>>>(wqm, wqv, wkm, wkv, wvm, wvv);
    prep_kernel<<<512, 256>>>(bqm, bqv, bkm, bkv, bvm, bvv);
    attn_kernel<<<dim3(8, 16), 256, ATTN_SMEM_BYTES>>>();
    out_gemm_mma<<<dim3(16, 8, 2), 256, GEMM_SMEM_B>>>(wom, wov);
    out_epilogue_kernel<<<dim3(256, 2), 256>>>(bom, bov, out);
}

// round 16
// speedup vs baseline: 1.0305x; 1.0305x over previous
#include <cuda_runtime.h>
#include <cuda_bf16.h>
#include <math.h>
#include <stdint.h>

#define L 256
#define D 1024
#define H 16
#define DH 64
#define LD (L*D)

// ---------------- device scratch (no allocations allowed) ----------------
__device__ __align__(16) __nv_bfloat16 g_act_hi[2*LD];   // mu, var  [m][k]
__device__ __align__(16) __nv_bfloat16 g_act_lo[2*LD];
__device__ __align__(16) __nv_bfloat16 g_O_hi[2*LD];     // Om, Ov bf16 splits
__device__ __align__(16) __nv_bfloat16 g_O_lo[2*LD];
__device__ float g_qkv_part[3*6*LD];   // [ksplit][gemm][L*D]
__device__ float g_out_part[4*2*LD];   // [ksplit][gemm][L*D]
// attention feature arrays (bf16 splits), layout [l][h][128]
__device__ __align__(16) __nv_bfloat16 g_Xq_hi[L*2048], g_Xq_lo[L*2048];
__device__ __align__(16) __nv_bfloat16 g_Xk_hi[L*2048], g_Xk_lo[L*2048];
// transposed V: [g(m/v)][h*64+d][l]
__device__ __align__(16) __nv_bfloat16 g_VT_hi[2*1024*L], g_VT_lo[2*1024*L];
__device__ float g_Ck[H*L];

// ---------------- helpers ----------------
__device__ __forceinline__ uint32_t smem_u32(const void* p) {
    uint32_t a;
    asm("{ .reg .u64 t; cvta.to.shared.u64 t, %1; cvt.u32.u64 %0, t; }" : "=r"(a) : "l"(p));
    return a;
}
__device__ __forceinline__ void ldsm_x4(uint32_t (&r)[4], uint32_t addr) {
    asm volatile("ldmatrix.sync.aligned.m8n8.x4.shared.b16 {%0,%1,%2,%3}, [%4];"
                 : "=r"(r[0]), "=r"(r[1]), "=r"(r[2]), "=r"(r[3]) : "r"(addr));
}
__device__ __forceinline__ void mma_bf16(float (&d)[4], const uint32_t (&a)[4],
                                         uint32_t b0, uint32_t b1) {
    asm volatile(
        "mma.sync.aligned.m16n8k16.row.col.f32.bf16.bf16.f32 "
        "{%0,%1,%2,%3}, {%4,%5,%6,%7}, {%8,%9}, {%0,%1,%2,%3};"
        : "+f"(d[0]), "+f"(d[1]), "+f"(d[2]), "+f"(d[3])
        : "r"(a[0]), "r"(a[1]), "r"(a[2]), "r"(a[3]), "r"(b0), "r"(b1));
}
__device__ __forceinline__ float softplusf(float x) {
    return fmaxf(x, 0.0f) + log1pf(expf(-fabsf(x)));
}
__device__ __forceinline__ void split_bf16(float f, __nv_bfloat16& hi, __nv_bfloat16& lo) {
    hi = __float2bfloat16(f);
    lo = __float2bfloat16(f - __bfloat162float(hi));
}
__device__ __forceinline__ void pack_pair(float a0, float a1, uint32_t& uhi, uint32_t& ulo) {
    union { __nv_bfloat16 b[2]; uint32_t u; } Hi, Lo;
    split_bf16(a0, Hi.b[0], Lo.b[0]);
    split_bf16(a1, Hi.b[1], Lo.b[1]);
    uhi = Hi.u; ulo = Lo.u;
}

// ---------------- HMMA bf16x3 GEMM with fused fp32->bf16 W split ----------
#define BK 32
#define PITCH 40
#define S_AHI 0
#define S_ALO (128*PITCH)
#define S_BHI (2*128*PITCH)
#define S_BLO (2*128*PITCH + 64*PITCH)
#define STAGE_H (2*128*PITCH + 2*64*PITCH)
#define GEMM_SMEM_B (2*STAGE_H*2)

__device__ void gemm_mma(const float* __restrict__ W,
                         const __nv_bfloat16* __restrict__ a_hi,
                         const __nv_bfloat16* __restrict__ a_lo,
                         float* __restrict__ Cpart,
                         int m0, int n0, int k0, int nchunks)
{
    extern __shared__ __nv_bfloat16 sh[];
    const uint32_t sbase = smem_u32(sh);
    const int tid = threadIdx.x;
    const int lane = tid & 31;
    const int wid  = tid >> 5;
    const int wm   = wid & 3;
    const int wn   = wid >> 2;

    float acc[2][4][4];
    #pragma unroll
    for (int mt = 0; mt < 2; mt++)
        #pragma unroll
        for (int nt = 0; nt < 4; nt++)
            #pragma unroll
            for (int r = 0; r < 4; r++) acc[mt][nt][r] = 0.0f;

    const int arow = tid >> 2;
    const int ac8  = (tid & 3) << 3;
    const int bn   = tid & 63;
    const int bkb  = (tid >> 6) << 3;

    uint4 ra_hi[2], ra_lo[2];
    float bw[8];

    auto LDG = [&](int c) {
        const int kg = k0 + c * BK;
        #pragma unroll
        for (int u = 0; u < 2; u++) {
            const size_t off = (size_t)(m0 + arow + u * 64) * D + kg + ac8;
            ra_hi[u] = *(const uint4*)(a_hi + off);
            ra_lo[u] = *(const uint4*)(a_lo + off);
        }
        const float* wp = W + (size_t)(kg + bkb) * D + n0 + bn;
        #pragma unroll
        for (int i = 0; i < 8; i++) bw[i] = wp[(size_t)i * D];
    };
    auto STS = [&](int buf) {
        __nv_bfloat16* s = sh + buf * STAGE_H;
        #pragma unroll
        for (int u = 0; u < 2; u++) {
            const int off = (arow + u * 64) * PITCH + ac8;
            *(uint4*)(s + S_AHI + off) = ra_hi[u];
            *(uint4*)(s + S_ALO + off) = ra_lo[u];
        }
        union { __nv_bfloat16 h[8]; uint4 u; } Hi, Lo;
        #pragma unroll
        for (int i = 0; i < 8; i++) split_bf16(bw[i], Hi.h[i], Lo.h[i]);
        const int boff = bn * PITCH + bkb;
        *(uint4*)(s + S_BHI + boff) = Hi.u;
        *(uint4*)(s + S_BLO + boff) = Lo.u;
    };

    const uint32_t a_lrow = (uint32_t)(wm * 32 + (lane & 15)) * PITCH;
    const uint32_t a_koff = (uint32_t)((lane >> 4) << 3);
    const uint32_t b_lrow = (uint32_t)(wn * 32 + ((lane >> 4) << 3) + (lane & 7)) * PITCH;
    const uint32_t b_koff = (uint32_t)(((lane >> 3) & 1) << 3);

    LDG(0); STS(0); __syncthreads();
    for (int c = 0; c < nchunks; c++) {
        const int cur = c & 1;
        if (c + 1 < nchunks) LDG(c + 1);
        const uint32_t sb = sbase + (uint32_t)cur * (STAGE_H * 2);
        #pragma unroll
        for (int ks = 0; ks < 2; ks++) {
            uint32_t ahi[2][4], alo[2][4], bhi[2][4], blo[2][4];
            #pragma unroll
            for (int mt = 0; mt < 2; mt++) {
                uint32_t ad = sb + (S_AHI + a_lrow + mt * 16 * PITCH + ks * 16 + a_koff) * 2;
                ldsm_x4(ahi[mt], ad);
                ldsm_x4(alo[mt], ad + (S_ALO - S_AHI) * 2);
            }
            #pragma unroll
            for (int p = 0; p < 2; p++) {
                uint32_t bd = sb + (S_BHI + b_lrow + p * 16 * PITCH + ks * 16 + b_koff) * 2;
                ldsm_x4(bhi[p], bd);
                ldsm_x4(blo[p], bd + (S_BLO - S_BHI) * 2);
            }
            #pragma unroll
            for (int mt = 0; mt < 2; mt++)
                #pragma unroll
                for (int nt = 0; nt < 4; nt++) {
                    const int p = nt >> 1, q = (nt & 1) * 2;
                    mma_bf16(acc[mt][nt], ahi[mt], bhi[p][q], bhi[p][q + 1]);
                    mma_bf16(acc[mt][nt], ahi[mt], blo[p][q], blo[p][q + 1]);
                    mma_bf16(acc[mt][nt], alo[mt], bhi[p][q], bhi[p][q + 1]);
                }
        }
        if (c + 1 < nchunks) STS(cur ^ 1);
        __syncthreads();
    }

    #pragma unroll
    for (int mt = 0; mt < 2; mt++)
        #pragma unroll
        for (int nt = 0; nt < 4; nt++) {
            const int r = m0 + wm * 32 + mt * 16 + (lane >> 2);
            const int cL = n0 + wn * 32 + nt * 8 + (lane & 3) * 2;
            *(float2*)(Cpart + (size_t)r * D + cL) =
                make_float2(acc[mt][nt][0], acc[mt][nt][1]);
            *(float2*)(Cpart + (size_t)(r + 8) * D + cL) =
                make_float2(acc[mt][nt][2], acc[mt][nt][3]);
        }
}

// QKV: 6 GEMMs, split-K 3 -> grid(16, 6, 6) = 288 CTAs (one balanced wave)
__global__ __launch_bounds__(256, 2) void qkv_gemm_mma(
    const float* wqm, const float* wqv, const float* wkm,
    const float* wkv, const float* wvm, const float* wvv)
{
    const int g = blockIdx.z;
    const int mt = blockIdx.y & 1, s = blockIdx.y >> 1;   // s in 0..2
    const float* W;
    switch (g) {
        case 0: W = wqm; break; case 1: W = wqv; break;
        case 2: W = wkm; break; case 3: W = wkv; break;
        case 4: W = wvm; break; default: W = wvv; break;
    }
    const int k0     = (s == 0) ? 0  : (s == 1) ? 352 : 704;
    const int nch    = (s == 2) ? 10 : 11;
    gemm_mma(W, g_act_hi + (size_t)(g & 1) * LD, g_act_lo + (size_t)(g & 1) * LD,
             g_qkv_part + (size_t)(s * 6 + g) * LD,
             mt * 128, blockIdx.x * 64, k0, nch);
}

// out: 2 GEMMs, split-K 4 -> grid(16, 8, 2) = 256 CTAs
__global__ __launch_bounds__(256, 2) void out_gemm_mma(const float* wom, const float* wov)
{
    const int g = blockIdx.z;
    const int mt = blockIdx.y & 1, s = blockIdx.y >> 1;   // s in 0..3
    gemm_mma(g ? wov : wom,
             g_O_hi + (size_t)g * LD, g_O_lo + (size_t)g * LD,
             g_out_part + (size_t)(s * 2 + g) * LD,
             mt * 128, blockIdx.x * 64, s * 256, 8);
}

// ---------------- activation convert ----------------
__global__ __launch_bounds__(256) void convert_act_kernel(const float* mu, const float* var)
{
    int t = blockIdx.x * 256 + threadIdx.x;
    int e = t * 4;
    const float* src = (e < LD) ? mu : var;
    float4 v = *(const float4*)(src + (e & (LD - 1)));
    float vv[4] = { v.x, v.y, v.z, v.w };
    union { __nv_bfloat16 h[4]; uint2 u; } Hi, Lo;
    #pragma unroll
    for (int i = 0; i < 4; i++) split_bf16(vv[i], Hi.h[i], Lo.h[i]);
    *(uint2*)(g_act_hi + e) = Hi.u;
    *(uint2*)(g_act_lo + e) = Lo.u;
}

// ---------------- prep: sum 3 splits + bias + act + attn features ----------
__global__ __launch_bounds__(256) void prep_kernel(
    const float* bqm, const float* bqv, const float* bkm, const float* bkv,
    const float* bvm, const float* bvv)
{
    int tid = blockIdx.x * 256 + threadIdx.x;
    int e0  = tid * 2;
    int l = e0 >> 10, col = e0 & (D - 1);
    int h = col >> 6, dd = col & 63;

    float2 v[6];
    #pragma unroll
    for (int g = 0; g < 6; g++) {
        float2 p0 = *(const float2*)(g_qkv_part + (size_t)(0 * 6 + g) * LD + e0);
        float2 p1 = *(const float2*)(g_qkv_part + (size_t)(1 * 6 + g) * LD + e0);
        float2 p2 = *(const float2*)(g_qkv_part + (size_t)(2 * 6 + g) * LD + e0);
        v[g] = make_float2(p0.x + p1.x + p2.x, p0.y + p1.y + p2.y);
    }
    float vals[6][2] = {
        { v[0].x + bqm[col], v[0].y + bqm[col + 1] },
        { v[1].x + bqv[col], v[1].y + bqv[col + 1] },
        { v[2].x + bkm[col], v[2].y + bkm[col + 1] },
        { v[3].x + bkv[col], v[3].y + bkv[col + 1] },
        { v[4].x + bvm[col], v[4].y + bvm[col + 1] },
        { v[5].x + bvv[col], v[5].y + bvv[col + 1] },
    };
    float Aq[2], nqm[2], f1[2], f2[2], vm[2], vvv[2];
    float c = 0.0f;
    #pragma unroll
    for (int u = 0; u < 2; u++) {
        float qm = vals[0][u];
        float qv = softplusf(vals[1][u]);
        float km = vals[2][u];
        float kv = softplusf(vals[3][u]);
        float inv = 1.0f / kv;
        Aq[u]  = 0.5f * (qm * qm + qv);
        nqm[u] = -qm;
        f1[u]  = inv;
        f2[u]  = km * inv;
        vm[u]  = vals[4][u];
        vvv[u] = softplusf(vals[5][u]);
        c += 0.5f * (km * km * inv + logf(kv));
    }

    size_t xq = (size_t)l * 2048 + h * 128 + dd;
    uint32_t uh, ul;
    pack_pair(Aq[0],  Aq[1],  uh, ul);
    *(uint32_t*)(g_Xq_hi + xq) = uh;  *(uint32_t*)(g_Xq_lo + xq) = ul;
    pack_pair(nqm[0], nqm[1], uh, ul);
    *(uint32_t*)(g_Xq_hi + xq + 64) = uh;  *(uint32_t*)(g_Xq_lo + xq + 64) = ul;
    pack_pair(f1[0],  f1[1],  uh, ul);
    *(uint32_t*)(g_Xk_hi + xq) = uh;  *(uint32_t*)(g_Xk_lo + xq) = ul;
    pack_pair(f2[0],  f2[1],  uh, ul);
    *(uint32_t*)(g_Xk_hi + xq + 64) = uh;  *(uint32_t*)(g_Xk_lo + xq + 64) = ul;

    size_t vr = (size_t)(h * 64 + dd) * L + l;
    __nv_bfloat16 bh, bl;
    split_bf16(vm[0],  bh, bl); g_VT_hi[vr]              = bh; g_VT_lo[vr]              = bl;
    split_bf16(vm[1],  bh, bl); g_VT_hi[vr + L]          = bh; g_VT_lo[vr + L]          = bl;
    split_bf16(vvv[0], bh, bl); g_VT_hi[262144 + vr]     = bh; g_VT_lo[262144 + vr]     = bl;
    split_bf16(vvv[1], bh, bl); g_VT_hi[262144 + vr + L] = bh; g_VT_lo[262144 + vr + L] = bl;

    #pragma unroll
    for (int off = 16; off; off >>= 1) c += __shfl_xor_sync(0xffffffffu, c, off);
    if ((threadIdx.x & 31) == 0) {
        int w = tid >> 5;
        int row = w >> 4, hh = w & 15;
        g_Ck[hh * L + row] = c;
    }
}

// ---------------- HMMA attention: per (q-tile-32, head) [R13 version] ------
// all offsets in halves unless noted
#define AP 40
#define CH_Q 1296     // 32*40+16
#define CH_K 10256    // 256*40+16
#define CH_V 2576     // 64*40+16
#define XQ_HI 0
#define XQ_LO 5184
#define XK_HI 10368
#define XK_LO 51392
#define P_HI  0
#define P_LO  10368
#define P2_HI 20736
#define P2_LO 31104
#define VM_HI 41472
#define VM_LO 51776
#define VV_HI 62080
#define VV_LO 72384
#define PVREDF 41344   // float index: [2][32][68]
#define REDF   46208   // float index: [32][9]
#define CKF    46496   // float index: [256]
#define ATTN_SMEM_BYTES 187008

__global__ __launch_bounds__(256) void attn_kernel()
{
    extern __shared__ __nv_bfloat16 sh[];
    float* shf = (float*)sh;
    const uint32_t sbase = smem_u32(sh);
    const int h = blockIdx.y, q0 = blockIdx.x * 32;
    const int tid = threadIdx.x, lane = tid & 31, wid = tid >> 5;
    const int r4 = lane >> 2;

    if (tid < 256) shf[CKF + tid] = g_Ck[h * L + tid];

    // ---- load Xq (32 rows) and Xk (256 rows), hi/lo, chunked k ----
    #pragma unroll
    for (int u = 0; u < 2; u++) {
        int idx = tid + u * 256;
        int row = idx >> 4, k = (idx & 15) * 8;
        int ch = k >> 5, wi = k & 31;
        size_t src = (size_t)(q0 + row) * 2048 + h * 128 + k;
        int dst = ch * CH_Q + row * AP + wi;
        *(uint4*)(sh + XQ_HI + dst) = *(const uint4*)(g_Xq_hi + src);
        *(uint4*)(sh + XQ_LO + dst) = *(const uint4*)(g_Xq_lo + src);
    }
    #pragma unroll
    for (int u = 0; u < 16; u++) {
        int idx = tid + u * 256;
        int row = idx >> 4, k = (idx & 15) * 8;
        int ch = k >> 5, wi = k & 31;
        size_t src = (size_t)row * 2048 + h * 128 + k;
        int dst = ch * CH_K + row * AP + wi;
        *(uint4*)(sh + XK_HI + dst) = *(const uint4*)(g_Xk_hi + src);
        *(uint4*)(sh + XK_LO + dst) = *(const uint4*)(g_Xk_lo + src);
    }
    __syncthreads();

    const uint32_t a_row = (uint32_t)(lane & 15) * AP;
    const uint32_t a_k   = (uint32_t)(lane >> 4) * 8;
    const uint32_t b_pat = (uint32_t)(((lane >> 4) << 3) + (lane & 7));
    const uint32_t b_k   = (uint32_t)((lane >> 3) & 1) * 8;
    const uint32_t b_row = (uint32_t)(wid * 32 + b_pat) * AP;

    // ---- scores S = Xq . Xk^T ----
    float acc[2][4][4];
    #pragma unroll
    for (int mt = 0; mt < 2; mt++)
        #pragma unroll
        for (int nt = 0; nt < 4; nt++)
            #pragma unroll
            for (int r = 0; r < 4; r++) acc[mt][nt][r] = 0.0f;

    #pragma unroll
    for (int c = 0; c < 4; c++)
        #pragma unroll
        for (int ks = 0; ks < 2; ks++) {
            uint32_t ahi[2][4], alo[2][4], bhi[2][4], blo[2][4];
            #pragma unroll
            for (int mt = 0; mt < 2; mt++) {
                uint32_t ad = sbase + (uint32_t)(XQ_HI + c * CH_Q + a_row + mt * 16 * AP + ks * 16 + a_k) * 2;
                ldsm_x4(ahi[mt], ad);
                ldsm_x4(alo[mt], ad + (XQ_LO - XQ_HI) * 2);
            }
            #pragma unroll
            for (int p = 0; p < 2; p++) {
                uint32_t bd = sbase + (uint32_t)(XK_HI + c * CH_K + b_row + p * 16 * AP + ks * 16 + b_k) * 2;
                ldsm_x4(bhi[p], bd);
                ldsm_x4(blo[p], bd + (XK_LO - XK_HI) * 2);
            }
            #pragma unroll
            for (int mt = 0; mt < 2; mt++)
                #pragma unroll
                for (int nt = 0; nt < 4; nt++) {
                    const int p = nt >> 1, q = (nt & 1) * 2;
                    mma_bf16(acc[mt][nt], ahi[mt], bhi[p][q], bhi[p][q + 1]);
                    mma_bf16(acc[mt][nt], ahi[mt], blo[p][q], blo[p][q + 1]);
                    mma_bf16(acc[mt][nt], alo[mt], bhi[p][q], bhi[p][q + 1]);
                }
        }

    // ---- s = -0.125*(acc + Ck[col]) ----
    #pragma unroll
    for (int nt = 0; nt < 4; nt++) {
        int c0 = wid * 32 + nt * 8 + (lane & 3) * 2;
        float ck0 = shf[CKF + c0], ck1 = shf[CKF + c0 + 1];
        #pragma unroll
        for (int mt = 0; mt < 2; mt++) {
            acc[mt][nt][0] = -0.125f * (acc[mt][nt][0] + ck0);
            acc[mt][nt][1] = -0.125f * (acc[mt][nt][1] + ck1);
            acc[mt][nt][2] = -0.125f * (acc[mt][nt][2] + ck0);
            acc[mt][nt][3] = -0.125f * (acc[mt][nt][3] + ck1);
        }
    }

    // ---- softmax over 256 cols (8 warps) ----
    float rmax[2][2], rinv[2][2];
    #pragma unroll
    for (int mt = 0; mt < 2; mt++)
        #pragma unroll
        for (int rh = 0; rh < 2; rh++) {
            float m = -1e30f;
            #pragma unroll
            for (int nt = 0; nt < 4; nt++)
                m = fmaxf(m, fmaxf(acc[mt][nt][rh * 2], acc[mt][nt][rh * 2 + 1]));
            m = fmaxf(m, __shfl_xor_sync(0xffffffffu, m, 1));
            m = fmaxf(m, __shfl_xor_sync(0xffffffffu, m, 2));
            if ((lane & 3) == 0)
                shf[REDF + (mt * 16 + rh * 8 + r4) * 9 + wid] = m;
        }
    __syncthreads();
    #pragma unroll
    for (int mt = 0; mt < 2; mt++)
        #pragma unroll
        for (int rh = 0; rh < 2; rh++) {
            int row = mt * 16 + rh * 8 + r4;
            float m = -1e30f;
            #pragma unroll
            for (int w = 0; w < 8; w++) m = fmaxf(m, shf[REDF + row * 9 + w]);
            rmax[mt][rh] = m;
        }
    __syncthreads();
    #pragma unroll
    for (int mt = 0; mt < 2; mt++)
        #pragma unroll
        for (int rh = 0; rh < 2; rh++) {
            float s = 0.0f;
            #pragma unroll
            for (int nt = 0; nt < 4; nt++) {
                float e0 = __expf(acc[mt][nt][rh * 2]     - rmax[mt][rh]);
                float e1 = __expf(acc[mt][nt][rh * 2 + 1] - rmax[mt][rh]);
                acc[mt][nt][rh * 2] = e0; acc[mt][nt][rh * 2 + 1] = e1;
                s += e0 + e1;
            }
            s += __shfl_xor_sync(0xffffffffu, s, 1);
            s += __shfl_xor_sync(0xffffffffu, s, 2);
            if ((lane & 3) == 0)
                shf[REDF + (mt * 16 + rh * 8 + r4) * 9 + wid] = s;
        }
    __syncthreads();
    #pragma unroll
    for (int mt = 0; mt < 2; mt++)
        #pragma unroll
        for (int rh = 0; rh < 2; rh++) {
            int row = mt * 16 + rh * 8 + r4;
            float s = 0.0f;
            #pragma unroll
            for (int w = 0; w < 8; w++) s += shf[REDF + row * 9 + w];
            rinv[mt][rh] = 1.0f / s;
        }

    // ---- write P, P^2 (hi/lo bf16) as A-operand chunks ----
    #pragma unroll
    for (int mt = 0; mt < 2; mt++)
        #pragma unroll
        for (int nt = 0; nt < 4; nt++) {
            int c0 = wid * 32 + nt * 8 + (lane & 3) * 2;
            int chp = c0 >> 5, wip = c0 & 31;
            #pragma unroll
            for (int rh = 0; rh < 2; rh++) {
                int row = mt * 16 + rh * 8 + r4;
                float pn0 = acc[mt][nt][rh * 2]     * rinv[mt][rh];
                float pn1 = acc[mt][nt][rh * 2 + 1] * rinv[mt][rh];
                uint32_t uh, ul;
                int ad = chp * CH_Q + row * AP + wip;
                pack_pair(pn0, pn1, uh, ul);
                *(uint32_t*)(sh + P_HI + ad) = uh;
                *(uint32_t*)(sh + P_LO + ad) = ul;
                pack_pair(pn0 * pn0, pn1 * pn1, uh, ul);
                *(uint32_t*)(sh + P2_HI + ad) = uh;
                *(uint32_t*)(sh + P2_LO + ad) = ul;
            }
        }
    __syncthreads();

    // ---- PV: out = P@Vm^T, P^2@Vv^T ----
    const int osel = wid >> 2, wkk = (wid >> 1) & 1, wn = wid & 1;
    const uint32_t PB_HI = osel ? P2_HI : P_HI;
    const uint32_t VB_HI = osel ? VV_HI : VM_HI;
    const uint32_t pv_brow = (uint32_t)(wn * 32 + b_pat) * AP;

    float acc2[2][4][4];
    #pragma unroll
    for (int mt = 0; mt < 2; mt++)
        #pragma unroll
        for (int nt = 0; nt < 4; nt++)
            #pragma unroll
            for (int r = 0; r < 4; r++) acc2[mt][nt][r] = 0.0f;

    for (int kp = 0; kp < 2; kp++) {
        if (kp) __syncthreads();
        #pragma unroll
        for (int u = 0; u < 4; u++) {
            int idx = tid + u * 256;
            int row = idx >> 4, k = (idx & 15) * 8;
            int ch = k >> 5, wi = k & 31;
            size_t src = (size_t)(h * 64 + row) * L + kp * 128 + k;
            int dst = ch * CH_V + row * AP + wi;
            *(uint4*)(sh + VM_HI + dst) = *(const uint4*)(g_VT_hi + src);
            *(uint4*)(sh + VM_LO + dst) = *(const uint4*)(g_VT_lo + src);
            *(uint4*)(sh + VV_HI + dst) = *(const uint4*)(g_VT_hi + 262144 + src);
            *(uint4*)(sh + VV_LO + dst) = *(const uint4*)(g_VT_lo + 262144 + src);
        }
        __syncthreads();
        #pragma unroll
        for (int c2 = 0; c2 < 2; c2++) {
            int gch = kp * 4 + wkk * 2 + c2;
            int lch = wkk * 2 + c2;
            #pragma unroll
            for (int ks = 0; ks < 2; ks++) {
                uint32_t phi[2][4], plo[2][4], vhi[2][4], vlo[2][4];
                #pragma unroll
                for (int mt = 0; mt < 2; mt++) {
                    uint32_t ad = sbase + (uint32_t)(PB_HI + gch * CH_Q + a_row + mt * 16 * AP + ks * 16 + a_k) * 2;
                    ldsm_x4(phi[mt], ad);
                    ldsm_x4(plo[mt], ad + (P_LO - P_HI) * 2);
                }
                #pragma unroll
                for (int p = 0; p < 2; p++) {
                    uint32_t bd = sbase + (uint32_t)(VB_HI + lch * CH_V + pv_brow + p * 16 * AP + ks * 16 + b_k) * 2;
                    ldsm_x4(vhi[p], bd);
                    ldsm_x4(vlo[p], bd + (VM_LO - VM_HI) * 2);
                }
                #pragma unroll
                for (int mt = 0; mt < 2; mt++)
                    #pragma unroll
                    for (int nt = 0; nt < 4; nt++) {
                        const int p = nt >> 1, q = (nt & 1) * 2;
                        mma_bf16(acc2[mt][nt], phi[mt], vhi[p][q], vhi[p][q + 1]);
                        mma_bf16(acc2[mt][nt], phi[mt], vlo[p][q], vlo[p][q + 1]);
                        mma_bf16(acc2[mt][nt], plo[mt], vhi[p][q], vhi[p][q + 1]);
                    }
            }
        }
    }
    __syncthreads();

    // ---- cross-warp k reduce + output ----
    if (wkk == 1) {
        #pragma unroll
        for (int mt = 0; mt < 2; mt++)
            #pragma unroll
            for (int nt = 0; nt < 4; nt++) {
                int row = mt * 16 + r4;
                int c0 = wn * 32 + nt * 8 + (lane & 3) * 2;
                int o = (osel * 32 + row) * 68 + c0;
                *(float2*)&shf[PVREDF + o] = make_float2(acc2[mt][nt][0], acc2[mt][nt][1]);
                *(float2*)&shf[PVREDF + o + 8 * 68] = make_float2(acc2[mt][nt][2], acc2[mt][nt][3]);
            }
    }
    __syncthreads();
    if (wkk == 0) {
        #pragma unroll
        for (int mt = 0; mt < 2; mt++)
            #pragma unroll
            for (int nt = 0; nt < 4; nt++) {
                int c0 = wn * 32 + nt * 8 + (lane & 3) * 2;
                #pragma unroll
                for (int rh = 0; rh < 2; rh++) {
                    int row = mt * 16 + rh * 8 + r4;
                    int o = (osel * 32 + row) * 68 + c0;
                    float v0 = acc2[mt][nt][rh * 2]     + shf[PVREDF + o];
                    float v1 = acc2[mt][nt][rh * 2 + 1] + shf[PVREDF + o + 1];
                    uint32_t uh, ul;
                    pack_pair(v0, v1, uh, ul);
                    size_t go = (size_t)osel * LD + (size_t)(q0 + row) * D + h * 64 + c0;
                    *(uint32_t*)(g_O_hi + go) = uh;
                    *(uint32_t*)(g_O_lo + go) = ul;
                }
            }
    }
}

// ---------------- output epilogue: sum 4 splits + bias + softplus ----------
__global__ __launch_bounds__(256) void out_epilogue_kernel(
    const float* bom, const float* bov, float* out)
{
    int g = blockIdx.y;
    int e = (blockIdx.x * 256 + threadIdx.x) * 4;
    float4 acc = make_float4(0.f, 0.f, 0.f, 0.f);
    #pragma unroll
    for (int s = 0; s < 4; s++) {
        float4 p = *(const float4*)(g_out_part + (size_t)(s * 2 + g) * LD + e);
        acc.x += p.x; acc.y += p.y; acc.z += p.z; acc.w += p.w;
    }
    int col = e & (D - 1);
    const float* b = g ? bov : bom;
    acc.x += b[col]; acc.y += b[col + 1]; acc.z += b[col + 2]; acc.w += b[col + 3];
    if (g) {
        acc.x = softplusf(acc.x); acc.y = softplusf(acc.y);
        acc.z = softplusf(acc.z); acc.w = softplusf(acc.w);
    }
    *(float4*)(out + (size_t)g * LD + e) = acc;
}

// ---------------- launch ----------------
extern "C" void kernel_launch(void* const* d_in, const int* in_sizes, int n_in,
                              void* d_out, int out_size)
{
    const float* mu  = (const float*)d_in[0];
    const float* var = (const float*)d_in[1];
    const float* wqm = (const float*)d_in[2],  * bqm = (const float*)d_in[3];
    const float* wqv = (const float*)d_in[4],  * bqv = (const float*)d_in[5];
    const float* wkm = (const float*)d_in[6],  * bkm = (const float*)d_in[7];
    const float* wkv = (const float*)d_in[8],  * bkv = (const float*)d_in[9];
    const float* wvm = (const float*)d_in[10], * bvm = (const float*)d_in[11];
    const float* wvv = (const float*)d_in[12], * bvv = (const float*)d_in[13];
    const float* wom = (const float*)d_in[14], * bom = (const float*)d_in[15];
    const float* wov = (const float*)d_in[16], * bov = (const float*)d_in[17];
    float* out = (float*)d_out;

    cudaFuncSetAttribute(qkv_gemm_mma, cudaFuncAttributeMaxDynamicSharedMemorySize, GEMM_SMEM_B);
    cudaFuncSetAttribute(out_gemm_mma, cudaFuncAttributeMaxDynamicSharedMemorySize, GEMM_SMEM_B);
    cudaFuncSetAttribute(attn_kernel, cudaFuncAttributeMaxDynamicSharedMemorySize, ATTN_SMEM_BYTES);

    convert_act_kernel<<<512, 256>>>(mu, var);
    qkv_gemm_mma<<<dim3(16, 6, 6), 256, GEMM_SMEM_B>>>(wqm, wqv, wkm, wkv, wvm, wvv);
    prep_kernel<<<512, 256>>>(bqm, bqv, bkm, bkv, bvm, bvv);
    attn_kernel<<<dim3(8, 16), 256, ATTN_SMEM_BYTES>>>();
    out_gemm_mma<<<dim3(16, 8, 2), 256, GEMM_SMEM_B>>>(wom, wov);
    out_epilogue_kernel<<<dim3(256, 2), 256>>>(bom, bov, out);
}